// round 1
// baseline (speedup 1.0000x reference)
#include <cuda_runtime.h>
#include <math.h>

#define Bb 2
#define Ss 2048
#define Dd 1024
#define Hh 16
#define HDd 64

// Scratch (static device globals -- no allocation at launch time)
__device__ float g_q[Bb * Hh * Ss * HDd];
__device__ float g_k[Bb * Hh * Ss * HDd];
__device__ float g_v[Bb * Hh * Ss * HDd];
__device__ float g_ctx[Bb * Ss * Dd];

// ---------------------------------------------------------------------------
// SGEMM: C[M,N] = A[M,K] * W[K,N] + bias, optional split-head store
// M = B*S = 4096, N = K = 1024.
// 128x128 block tile, BK=8, 8x8 per-thread microtile, 256 threads.
// ---------------------------------------------------------------------------
#define GBM 128
#define GBN 128
#define GBK 8
#define GTM 8
#define GTN 8

__global__ __launch_bounds__(256) void gemm_bias(
    const float* __restrict__ Aext, const float* __restrict__ W,
    const float* __restrict__ bias, float* __restrict__ Cext,
    int dst, int split)
{
    const int N = Dd, Kd = Dd;
    const float* A = Aext ? Aext : g_ctx;
    float* C = (dst == 0) ? g_q : (dst == 1) ? g_k : (dst == 2) ? g_v : Cext;

    __shared__ float As[GBK][GBM];   // A tile, transposed
    __shared__ float Bs[GBK][GBN];

    int tid  = threadIdx.x;
    int brow = blockIdx.y * GBM;
    int bcol = blockIdx.x * GBN;

    int aRow = tid >> 1;            // 0..127
    int aCol = (tid & 1) * 4;       // 0 or 4
    int bRow = tid >> 5;            // 0..7
    int bCol = (tid & 31) * 4;      // 0..124
    int ty = tid >> 4, tx = tid & 15;

    float acc[GTM][GTN];
#pragma unroll
    for (int i = 0; i < GTM; i++)
#pragma unroll
        for (int j = 0; j < GTN; j++) acc[i][j] = 0.0f;

    for (int k0 = 0; k0 < Kd; k0 += GBK) {
        float4 a4 = *(const float4*)(A + (size_t)(brow + aRow) * Kd + k0 + aCol);
        As[aCol + 0][aRow] = a4.x;
        As[aCol + 1][aRow] = a4.y;
        As[aCol + 2][aRow] = a4.z;
        As[aCol + 3][aRow] = a4.w;
        *(float4*)&Bs[bRow][bCol] =
            *(const float4*)(W + (size_t)(k0 + bRow) * N + bcol + bCol);
        __syncthreads();

#pragma unroll
        for (int k = 0; k < GBK; k++) {
            float4 am0 = *(float4*)&As[k][ty * GTM];
            float4 am1 = *(float4*)&As[k][ty * GTM + 4];
            float4 bn0 = *(float4*)&Bs[k][tx * GTN];
            float4 bn1 = *(float4*)&Bs[k][tx * GTN + 4];
            float am[GTM] = {am0.x, am0.y, am0.z, am0.w, am1.x, am1.y, am1.z, am1.w};
            float bn[GTN] = {bn0.x, bn0.y, bn0.z, bn0.w, bn1.x, bn1.y, bn1.z, bn1.w};
#pragma unroll
            for (int i = 0; i < GTM; i++)
#pragma unroll
                for (int j = 0; j < GTN; j++)
                    acc[i][j] = fmaf(am[i], bn[j], acc[i][j]);
        }
        __syncthreads();
    }

#pragma unroll
    for (int i = 0; i < GTM; i++) {
        int row = brow + ty * GTM + i;
        int b = row / Ss, s = row % Ss;
#pragma unroll
        for (int j = 0; j < GTN; j += 4) {
            int col = bcol + tx * GTN + j;
            float4 v;
            v.x = acc[i][j + 0] + bias[col + 0];
            v.y = acc[i][j + 1] + bias[col + 1];
            v.z = acc[i][j + 2] + bias[col + 2];
            v.w = acc[i][j + 3] + bias[col + 3];
            if (split) {
                int h = col >> 6, hd = col & 63;   // 8-wide groups never cross 64
                *(float4*)&C[(((size_t)b * Hh + h) * Ss + s) * HDd + hd] = v;
            } else {
                *(float4*)&C[(size_t)row * N + col] = v;
            }
        }
    }
}

// ---------------------------------------------------------------------------
// Causal flash attention, fp32. One block = 64 q-rows of one (b,h).
// Online softmax in log2 domain, scale (1/32)*log2(e) folded in.
// ---------------------------------------------------------------------------
#define FBM 64
#define FBN 32
#define SCALE_L2E (0.03125f * 1.4426950408889634f)

__global__ __launch_bounds__(256) void flash_attn()
{
    __shared__ float Qs[FBM][HDd + 4];
    __shared__ float Ks[FBN][HDd + 4];
    __shared__ float Vs[FBN][HDd + 4];
    __shared__ float Ps[FBM][FBN + 4];
    __shared__ float rowm[FBM], rowl[FBM], rowa[FBM];

    int tid   = threadIdx.x;
    int qtile = blockIdx.x;
    int bh    = blockIdx.y;
    int ty = tid >> 4, tx = tid & 15;

    const float* qb = g_q + (size_t)bh * Ss * HDd + (size_t)qtile * FBM * HDd;
    const float* kb = g_k + (size_t)bh * Ss * HDd;
    const float* vb = g_v + (size_t)bh * Ss * HDd;

    // load Q tile (64 x 64)
    for (int idx = tid; idx < FBM * (HDd / 4); idx += 256) {
        int r = idx >> 4, c4 = (idx & 15) * 4;
        *(float4*)&Qs[r][c4] = *(const float4*)(qb + r * HDd + c4);
    }
    if (tid < FBM) { rowm[tid] = -INFINITY; rowl[tid] = 0.0f; }

    float o[4][4];
#pragma unroll
    for (int i = 0; i < 4; i++)
#pragma unroll
        for (int j = 0; j < 4; j++) o[i][j] = 0.0f;

    int jmax = 2 * qtile + 1;   // last kv tile intersecting the causal triangle
    for (int j = 0; j <= jmax; j++) {
        __syncthreads();   // previous iteration's smem reads finished
        for (int idx = tid; idx < FBN * (HDd / 4); idx += 256) {
            int r = idx >> 4, c4 = (idx & 15) * 4;
            int src = (j * FBN + r) * HDd + c4;
            *(float4*)&Ks[r][c4] = *(const float4*)(kb + src);
            *(float4*)&Vs[r][c4] = *(const float4*)(vb + src);
        }
        __syncthreads();

        // S tile: rows ty*4..+4, cols tx*2..+2
        float s[4][2];
#pragma unroll
        for (int i = 0; i < 4; i++) { s[i][0] = 0.0f; s[i][1] = 0.0f; }
#pragma unroll
        for (int d4 = 0; d4 < HDd / 4; d4++) {
            float4 qv[4], kv[2];
#pragma unroll
            for (int i = 0; i < 4; i++) qv[i] = *(float4*)&Qs[ty * 4 + i][d4 * 4];
#pragma unroll
            for (int jj = 0; jj < 2; jj++) kv[jj] = *(float4*)&Ks[tx * 2 + jj][d4 * 4];
#pragma unroll
            for (int i = 0; i < 4; i++)
#pragma unroll
                for (int jj = 0; jj < 2; jj++) {
                    s[i][jj] = fmaf(qv[i].x, kv[jj].x, s[i][jj]);
                    s[i][jj] = fmaf(qv[i].y, kv[jj].y, s[i][jj]);
                    s[i][jj] = fmaf(qv[i].z, kv[jj].z, s[i][jj]);
                    s[i][jj] = fmaf(qv[i].w, kv[jj].w, s[i][jj]);
                }
        }
        bool needMask = (j * FBN + FBN - 1 > qtile * FBM);
#pragma unroll
        for (int i = 0; i < 4; i++)
#pragma unroll
            for (int jj = 0; jj < 2; jj++) {
                float t = s[i][jj] * SCALE_L2E;
                if (needMask) {
                    int kg = j * FBN + tx * 2 + jj;
                    int qg = qtile * FBM + ty * 4 + i;
                    if (kg > qg) t = -1e30f;
                }
                Ps[ty * 4 + i][tx * 2 + jj] = t;
            }
        __syncthreads();

        // per-row online softmax update (64 row-owner threads)
        if (tid < FBM) {
            float mold = rowm[tid];
            float mnew = mold;
#pragma unroll
            for (int c = 0; c < FBN; c++) mnew = fmaxf(mnew, Ps[tid][c]);
            float a = exp2f(mold - mnew);
            float sum = 0.0f;
#pragma unroll
            for (int c = 0; c < FBN; c++) {
                float p = exp2f(Ps[tid][c] - mnew);
                Ps[tid][c] = p;
                sum += p;
            }
            rowl[tid] = rowl[tid] * a + sum;
            rowm[tid] = mnew;
            rowa[tid] = a;
        }
        __syncthreads();

        // rescale O and accumulate P @ V : rows ty*4..+4, cols tx*4..+4
#pragma unroll
        for (int i = 0; i < 4; i++) {
            float a = rowa[ty * 4 + i];
            o[i][0] *= a; o[i][1] *= a; o[i][2] *= a; o[i][3] *= a;
        }
#pragma unroll
        for (int c = 0; c < FBN; c++) {
            float4 vv = *(float4*)&Vs[c][tx * 4];
#pragma unroll
            for (int i = 0; i < 4; i++) {
                float p = Ps[ty * 4 + i][c];
                o[i][0] = fmaf(p, vv.x, o[i][0]);
                o[i][1] = fmaf(p, vv.y, o[i][1]);
                o[i][2] = fmaf(p, vv.z, o[i][2]);
                o[i][3] = fmaf(p, vv.w, o[i][3]);
            }
        }
    }

    // write context with merged-head layout [B, S, D]
    int b = bh / Hh, h = bh % Hh;
#pragma unroll
    for (int i = 0; i < 4; i++) {
        int qg = qtile * FBM + ty * 4 + i;
        float inv = 1.0f / rowl[ty * 4 + i];
        float4 v;
        v.x = o[i][0] * inv;
        v.y = o[i][1] * inv;
        v.z = o[i][2] * inv;
        v.w = o[i][3] * inv;
        *(float4*)&g_ctx[((size_t)b * Ss + qg) * Dd + h * HDd + tx * 4] = v;
    }
}

// ---------------------------------------------------------------------------
// Input order (metadata): K, V, Q, mask, Wk, bk, Wv, bv, Wq, bq, Wo, bo
// ---------------------------------------------------------------------------
extern "C" void kernel_launch(void* const* d_in, const int* in_sizes, int n_in,
                              void* d_out, int out_size)
{
    const float* K  = (const float*)d_in[0];
    const float* V  = (const float*)d_in[1];
    const float* Q  = (const float*)d_in[2];
    const float* Wk = (const float*)d_in[4];
    const float* bk = (const float*)d_in[5];
    const float* Wv = (const float*)d_in[6];
    const float* bv = (const float*)d_in[7];
    const float* Wq = (const float*)d_in[8];
    const float* bq = (const float*)d_in[9];
    const float* Wo = (const float*)d_in[10];
    const float* bo = (const float*)d_in[11];
    float* out = (float*)d_out;

    dim3 gg(Dd / GBN, (Bb * Ss) / GBM);
    gemm_bias<<<gg, 256>>>(Q, Wq, bq, nullptr, 0, 1);
    gemm_bias<<<gg, 256>>>(K, Wk, bk, nullptr, 1, 1);
    gemm_bias<<<gg, 256>>>(V, Wv, bv, nullptr, 2, 1);
    flash_attn<<<dim3(Ss / FBM, Bb * Hh), 256>>>();
    gemm_bias<<<gg, 256>>>(nullptr, Wo, bo, out, 3, 0);
}

// round 3
// speedup vs baseline: 1.3107x; 1.3107x over previous
#include <cuda_runtime.h>
#include <cuda_bf16.h>
#include <math.h>
#include <stdint.h>

#define Bb 2
#define Ss 2048
#define Dd 1024
#define Hh 16
#define HDd 64
#define Mm (Bb * Ss)

// ---------------- scratch (device globals; no allocation) ----------------
__device__ __align__(16) float g_q[Bb * Hh * Ss * HDd];
__device__ __align__(16) float g_k[Bb * Hh * Ss * HDd];
__device__ __align__(16) float g_v[Bb * Hh * Ss * HDd];
__device__ __align__(16) float g_ctx[Bb * Ss * Dd];
__device__ __align__(16) __nv_bfloat16 g_ah[Mm * Dd];
__device__ __align__(16) __nv_bfloat16 g_al[Mm * Dd];
__device__ __align__(16) __nv_bfloat16 g_bh[Dd * Dd];
__device__ __align__(16) __nv_bfloat16 g_bl[Dd * Dd];

// ---------------- helpers ----------------
static __device__ __forceinline__ uint32_t s2u(const void* p) {
    uint32_t a;
    asm("{ .reg .u64 t; cvta.to.shared.u64 t, %1; cvt.u32.u64 %0, t; }"
        : "=r"(a) : "l"(p));
    return a;
}
static __device__ __forceinline__ float ex2(float x) {
    float y;
    asm("ex2.approx.ftz.f32 %0, %1;" : "=f"(y) : "f"(x));
    return y;
}

#define LDSM_X4(R, addr)                                                        \
    asm volatile("ldmatrix.sync.aligned.m8n8.x4.shared.b16 {%0,%1,%2,%3}, [%4];"\
        : "=r"((R)[0]), "=r"((R)[1]), "=r"((R)[2]), "=r"((R)[3]) : "r"(addr))

static __device__ __forceinline__ void mma_bf16(
    float* c, const uint32_t* a, const uint32_t* b)
{
    asm volatile(
        "mma.sync.aligned.m16n8k16.row.col.f32.bf16.bf16.f32 "
        "{%0,%1,%2,%3}, {%4,%5,%6,%7}, {%8,%9}, {%0,%1,%2,%3};"
        : "+f"(c[0]), "+f"(c[1]), "+f"(c[2]), "+f"(c[3])
        : "r"(a[0]), "r"(a[1]), "r"(a[2]), "r"(a[3]), "r"(b[0]), "r"(b[1]));
}

// ---------------- split kernels (fp32 -> bf16 hi/lo) ----------------
__global__ __launch_bounds__(256) void split_a(const float* __restrict__ src)
{
    const float* A = src ? src : g_ctx;
    int i = (blockIdx.x * 256 + threadIdx.x) * 4;
    float4 v = *(const float4*)(A + i);
    union { __nv_bfloat16 b[4]; uint2 u; } h, l;
    float x;
    x = v.x; h.b[0] = __float2bfloat16(x); l.b[0] = __float2bfloat16(x - __bfloat162float(h.b[0]));
    x = v.y; h.b[1] = __float2bfloat16(x); l.b[1] = __float2bfloat16(x - __bfloat162float(h.b[1]));
    x = v.z; h.b[2] = __float2bfloat16(x); l.b[2] = __float2bfloat16(x - __bfloat162float(h.b[2]));
    x = v.w; h.b[3] = __float2bfloat16(x); l.b[3] = __float2bfloat16(x - __bfloat162float(h.b[3]));
    *(uint2*)(g_ah + i) = h.u;
    *(uint2*)(g_al + i) = l.u;
}

// W[K,N] fp32 -> bh/bl[N,K] bf16 (transposed)
__global__ __launch_bounds__(256) void split_wT(const float* __restrict__ W)
{
    __shared__ float t[32][33];
    int n0 = blockIdx.x * 32, k0 = blockIdx.y * 32;
    int tx = threadIdx.x & 31, ty = threadIdx.x >> 5;
#pragma unroll
    for (int r = ty; r < 32; r += 8)
        t[r][tx] = W[(size_t)(k0 + r) * Dd + n0 + tx];
    __syncthreads();
#pragma unroll
    for (int r = ty; r < 32; r += 8) {
        float x = t[tx][r];  // = W[k0+tx][n0+r]
        __nv_bfloat16 h = __float2bfloat16(x);
        __nv_bfloat16 l = __float2bfloat16(x - __bfloat162float(h));
        size_t o = (size_t)(n0 + r) * Dd + k0 + tx;
        g_bh[o] = h;
        g_bl[o] = l;
    }
}

// ---------------- mma.sync GEMM: C[M,N] = A*W + bias ----------------
// A(hi/lo) g_ah/g_al [M,K]; B(hi/lo) g_bh/g_bl [N,K] (K-major both).
// 3 passes: ah*bh + al*bh + ah*bl, fp32 accumulators in registers.
#define GBM 128
#define GBN 128
#define GBK 32
#define AROW 40          // bf16 elems per padded smem row (80 bytes)
#define TILEB (128 * AROW * 2)      // 10240 bytes per tile
#define STAGEB (4 * TILEB)          // ah, al, bh, bl
#define GEMM_SMEM (2 * STAGEB)      // 81920

__global__ __launch_bounds__(256) void gemm_tc(
    const float* __restrict__ bias, float* __restrict__ Cext, int dst, int split)
{
    extern __shared__ char smem[];
    const int tid = threadIdx.x, wid = tid >> 5, lane = tid & 31;
    const int warpM = wid & 3, warpN = wid >> 2;       // 4 x 2 warps
    const int brow = blockIdx.y * GBM, bcol = blockIdx.x * GBN;
    const uint32_t sb = s2u(smem);

    float acc[2][8][4];
#pragma unroll
    for (int mf = 0; mf < 2; mf++)
#pragma unroll
        for (int nf = 0; nf < 8; nf++)
#pragma unroll
            for (int q = 0; q < 4; q++) acc[mf][nf][q] = 0.0f;

    // per-thread load role: 64 threads per tile, 8 chunks of 16B each
    const int t = tid >> 6;                    // tile: 0 ah, 1 al, 2 bh, 3 bl
    const __nv_bfloat16* src = (t == 0) ? g_ah : (t == 1) ? g_al
                             : (t == 2) ? g_bh : g_bl;
    const int rb = (t < 2) ? brow : bcol;
    const int lbase = tid & 63;

#define LOAD_CHUNK(c) do {                                                     \
    int k0_ = (c) * GBK;                                                       \
    uint32_t st_ = sb + ((c) & 1) * STAGEB + t * TILEB;                        \
    _Pragma("unroll")                                                          \
    for (int i_ = 0; i_ < 8; i_++) {                                           \
        int idx_ = lbase + i_ * 64;                                            \
        int row_ = idx_ >> 2, cc_ = idx_ & 3;                                  \
        const void* g_ = src + (size_t)(rb + row_) * Dd + k0_ + cc_ * 8;       \
        uint32_t s_ = st_ + row_ * 80 + cc_ * 16;                              \
        asm volatile("cp.async.cg.shared.global [%0], [%1], 16;"               \
                     :: "r"(s_), "l"(g_));                                     \
    }                                                                          \
    asm volatile("cp.async.commit_group;");                                    \
} while (0)

    LOAD_CHUNK(0);

    const int NKC = Dd / GBK;   // 32
    for (int c = 0; c < NKC; c++) {
        if (c + 1 < NKC) {
            LOAD_CHUNK(c + 1);
            asm volatile("cp.async.wait_group 1;");
        } else {
            asm volatile("cp.async.wait_group 0;");
        }
        __syncthreads();

        const uint32_t stage = sb + (c & 1) * STAGEB;
        // ldmatrix lane addressing
        const int arow = warpM * 32 + (lane & 15);
        const int acolb = ((lane >> 4) & 1) * 16;          // bytes (k +0 / +8)
        const int bn = warpN * 64 + (lane & 7) + ((lane & 16) ? 8 : 0);
        const int bkb = ((lane & 8) ? 16 : 0);             // bytes

#pragma unroll
        for (int ks = 0; ks < 2; ks++) {
            const int kb = ks * 32;                         // 16 elems = 32 bytes
            uint32_t ah[2][4], al[2][4], bh[4][4], bl[4][4];
#pragma unroll
            for (int mf = 0; mf < 2; mf++) {
                uint32_t ad = stage + (arow + mf * 16) * 80 + kb + acolb;
                LDSM_X4(ah[mf], ad);
                LDSM_X4(al[mf], ad + TILEB);
            }
#pragma unroll
            for (int nb = 0; nb < 4; nb++) {
                uint32_t bd = stage + 2 * TILEB + (bn + nb * 16) * 80 + kb + bkb;
                LDSM_X4(bh[nb], bd);
                LDSM_X4(bl[nb], bd + TILEB);
            }
#pragma unroll
            for (int mf = 0; mf < 2; mf++)
#pragma unroll
                for (int nf = 0; nf < 8; nf++) {
                    const uint32_t* bhp = &bh[nf >> 1][(nf & 1) * 2];
                    const uint32_t* blp = &bl[nf >> 1][(nf & 1) * 2];
                    mma_bf16(acc[mf][nf], ah[mf], bhp);
                    mma_bf16(acc[mf][nf], al[mf], bhp);
                    mma_bf16(acc[mf][nf], ah[mf], blp);
                }
        }
        __syncthreads();
    }

    // epilogue: bias + store (optionally split heads)
    float* C = (dst == 0) ? g_q : (dst == 1) ? g_k : (dst == 2) ? g_v : Cext;
#pragma unroll
    for (int mf = 0; mf < 2; mf++) {
        int r0 = brow + warpM * 32 + mf * 16 + (lane >> 2);
#pragma unroll
        for (int nf = 0; nf < 8; nf++) {
            int col = bcol + warpN * 64 + nf * 8 + (lane & 3) * 2;
            float bx = bias[col], by = bias[col + 1];
            float2 v0 = make_float2(acc[mf][nf][0] + bx, acc[mf][nf][1] + by);
            float2 v1 = make_float2(acc[mf][nf][2] + bx, acc[mf][nf][3] + by);
            if (split) {
                int h = col >> 6, hd = col & 63;
                int b0 = r0 >> 11, s0 = r0 & 2047;
                int b1 = (r0 + 8) >> 11, s1 = (r0 + 8) & 2047;
                *(float2*)&C[(((size_t)b0 * Hh + h) * Ss + s0) * HDd + hd] = v0;
                *(float2*)&C[(((size_t)b1 * Hh + h) * Ss + s1) * HDd + hd] = v1;
            } else {
                *(float2*)&C[(size_t)r0 * Dd + col] = v0;
                *(float2*)&C[(size_t)(r0 + 8) * Dd + col] = v1;
            }
        }
    }
}

// ---------------- causal flash attention (fp32 SIMT) ----------------
#define FBM 64
#define FBN 32
#define SCALE_L2E (0.03125f * 1.4426950408889634f)

__global__ __launch_bounds__(256) void flash_attn()
{
    __shared__ float Qs[FBM][HDd + 4];
    __shared__ float Ks[FBN][HDd + 4];
    __shared__ float Vs[FBN][HDd + 4];
    __shared__ float Ps[FBM][FBN + 4];
    __shared__ float pmax[FBM][5], psum[FBM][5];
    __shared__ float rowm[FBM], rowl[FBM], rowa[FBM];

    int tid   = threadIdx.x;
    int qtile = blockIdx.x;
    int bh    = blockIdx.y;
    int ty = tid >> 4, tx = tid & 15;

    const float* qb = g_q + (size_t)bh * Ss * HDd + (size_t)qtile * FBM * HDd;
    const float* kb = g_k + (size_t)bh * Ss * HDd;
    const float* vb = g_v + (size_t)bh * Ss * HDd;

    for (int idx = tid; idx < FBM * (HDd / 4); idx += 256) {
        int r = idx >> 4, c4 = (idx & 15) * 4;
        *(float4*)&Qs[r][c4] = *(const float4*)(qb + r * HDd + c4);
    }
    if (tid < FBM) { rowm[tid] = -INFINITY; rowl[tid] = 0.0f; }

    float o[4][4];
#pragma unroll
    for (int i = 0; i < 4; i++)
#pragma unroll
        for (int j = 0; j < 4; j++) o[i][j] = 0.0f;

    int jmax = 2 * qtile + 1;
    for (int j = 0; j <= jmax; j++) {
        __syncthreads();
        for (int idx = tid; idx < FBN * (HDd / 4); idx += 256) {
            int r = idx >> 4, c4 = (idx & 15) * 4;
            int src = (j * FBN + r) * HDd + c4;
            *(float4*)&Ks[r][c4] = *(const float4*)(kb + src);
            *(float4*)&Vs[r][c4] = *(const float4*)(vb + src);
        }
        __syncthreads();

        // S tile: rows ty*4..+4, cols tx*2..+2
        float s[4][2];
#pragma unroll
        for (int i = 0; i < 4; i++) { s[i][0] = 0.0f; s[i][1] = 0.0f; }
#pragma unroll
        for (int d4 = 0; d4 < HDd / 4; d4++) {
            float4 qv[4], kv[2];
#pragma unroll
            for (int i = 0; i < 4; i++) qv[i] = *(float4*)&Qs[ty * 4 + i][d4 * 4];
#pragma unroll
            for (int jj = 0; jj < 2; jj++) kv[jj] = *(float4*)&Ks[tx * 2 + jj][d4 * 4];
#pragma unroll
            for (int i = 0; i < 4; i++)
#pragma unroll
                for (int jj = 0; jj < 2; jj++) {
                    s[i][jj] = fmaf(qv[i].x, kv[jj].x, s[i][jj]);
                    s[i][jj] = fmaf(qv[i].y, kv[jj].y, s[i][jj]);
                    s[i][jj] = fmaf(qv[i].z, kv[jj].z, s[i][jj]);
                    s[i][jj] = fmaf(qv[i].w, kv[jj].w, s[i][jj]);
                }
        }
        bool needMask = (j * FBN + FBN - 1 > qtile * FBM);
#pragma unroll
        for (int i = 0; i < 4; i++)
#pragma unroll
            for (int jj = 0; jj < 2; jj++) {
                float t = s[i][jj] * SCALE_L2E;
                if (needMask) {
                    int kg = j * FBN + tx * 2 + jj;
                    int qg = qtile * FBM + ty * 4 + i;
                    if (kg > qg) t = -1e30f;
                }
                Ps[ty * 4 + i][tx * 2 + jj] = t;
            }
        __syncthreads();

        // parallel online softmax: 4 threads per row, 8 cols each
        {
            int row = tid & 63, qq = tid >> 6;
            float pm = Ps[row][qq * 8];
#pragma unroll
            for (int c = 1; c < 8; c++) pm = fmaxf(pm, Ps[row][qq * 8 + c]);
            pmax[row][qq] = pm;
        }
        __syncthreads();
        {
            int row = tid & 63, qq = tid >> 6;
            float mnew = fmaxf(fmaxf(fmaxf(pmax[row][0], pmax[row][1]),
                                     fmaxf(pmax[row][2], pmax[row][3])), rowm[row]);
            float sum = 0.0f;
#pragma unroll
            for (int c = 0; c < 8; c++) {
                float p = ex2(Ps[row][qq * 8 + c] - mnew);
                Ps[row][qq * 8 + c] = p;
                sum += p;
            }
            psum[row][qq] = sum;
        }
        __syncthreads();
        if (tid < FBM) {
            float mold = rowm[tid];
            float mnew = fmaxf(fmaxf(fmaxf(pmax[tid][0], pmax[tid][1]),
                                     fmaxf(pmax[tid][2], pmax[tid][3])), mold);
            float a = ex2(mold - mnew);
            rowl[tid] = rowl[tid] * a +
                        psum[tid][0] + psum[tid][1] + psum[tid][2] + psum[tid][3];
            rowm[tid] = mnew;
            rowa[tid] = a;
        }
        __syncthreads();

        // rescale O and accumulate P @ V (float4 P rows, 4-col blocks)
#pragma unroll
        for (int i = 0; i < 4; i++) {
            float a = rowa[ty * 4 + i];
            o[i][0] *= a; o[i][1] *= a; o[i][2] *= a; o[i][3] *= a;
        }
#pragma unroll
        for (int c4 = 0; c4 < FBN; c4 += 4) {
            float4 pv[4];
#pragma unroll
            for (int i = 0; i < 4; i++) pv[i] = *(float4*)&Ps[ty * 4 + i][c4];
            float4 v0 = *(float4*)&Vs[c4 + 0][tx * 4];
            float4 v1 = *(float4*)&Vs[c4 + 1][tx * 4];
            float4 v2 = *(float4*)&Vs[c4 + 2][tx * 4];
            float4 v3 = *(float4*)&Vs[c4 + 3][tx * 4];
#pragma unroll
            for (int i = 0; i < 4; i++) {
                o[i][0] = fmaf(pv[i].x, v0.x, fmaf(pv[i].y, v1.x,
                          fmaf(pv[i].z, v2.x, fmaf(pv[i].w, v3.x, o[i][0]))));
                o[i][1] = fmaf(pv[i].x, v0.y, fmaf(pv[i].y, v1.y,
                          fmaf(pv[i].z, v2.y, fmaf(pv[i].w, v3.y, o[i][1]))));
                o[i][2] = fmaf(pv[i].x, v0.z, fmaf(pv[i].y, v1.z,
                          fmaf(pv[i].z, v2.z, fmaf(pv[i].w, v3.z, o[i][2]))));
                o[i][3] = fmaf(pv[i].x, v0.w, fmaf(pv[i].y, v1.w,
                          fmaf(pv[i].z, v2.w, fmaf(pv[i].w, v3.w, o[i][3]))));
            }
        }
    }

    int b = bh / Hh, h = bh % Hh;
#pragma unroll
    for (int i = 0; i < 4; i++) {
        int qg = qtile * FBM + ty * 4 + i;
        float inv = 1.0f / rowl[ty * 4 + i];
        float4 v;
        v.x = o[i][0] * inv;
        v.y = o[i][1] * inv;
        v.z = o[i][2] * inv;
        v.w = o[i][3] * inv;
        *(float4*)&g_ctx[((size_t)b * Ss + qg) * Dd + h * HDd + tx * 4] = v;
    }
}

// ---------------- launch ----------------
// Input order: K, V, Q, mask, Wk, bk, Wv, bv, Wq, bq, Wo, bo
extern "C" void kernel_launch(void* const* d_in, const int* in_sizes, int n_in,
                              void* d_out, int out_size)
{
    const float* K  = (const float*)d_in[0];
    const float* V  = (const float*)d_in[1];
    const float* Q  = (const float*)d_in[2];
    const float* Wk = (const float*)d_in[4];
    const float* bk = (const float*)d_in[5];
    const float* Wv = (const float*)d_in[6];
    const float* bv = (const float*)d_in[7];
    const float* Wq = (const float*)d_in[8];
    const float* bq = (const float*)d_in[9];
    const float* Wo = (const float*)d_in[10];
    const float* bo = (const float*)d_in[11];
    float* out = (float*)d_out;

    static int cfg = 0;
    if (!cfg) {
        cudaFuncSetAttribute(gemm_tc, cudaFuncAttributeMaxDynamicSharedMemorySize, GEMM_SMEM);
        cfg = 1;
    }

    dim3 gg(Dd / GBN, Mm / GBM);       // (8, 32)
    dim3 gw(Dd / 32, Dd / 32);         // (32, 32)
    int  ga = (Mm * Dd) / (256 * 4);   // 4096

    split_a<<<ga, 256>>>(Q);
    split_wT<<<gw, 256>>>(Wq);
    gemm_tc<<<gg, 256, GEMM_SMEM>>>(bq, nullptr, 0, 1);

    split_a<<<ga, 256>>>(K);
    split_wT<<<gw, 256>>>(Wk);
    gemm_tc<<<gg, 256, GEMM_SMEM>>>(bk, nullptr, 1, 1);

    split_a<<<ga, 256>>>(V);
    split_wT<<<gw, 256>>>(Wv);
    gemm_tc<<<gg, 256, GEMM_SMEM>>>(bv, nullptr, 2, 1);

    flash_attn<<<dim3(Ss / FBM, Bb * Hh), 256>>>();

    split_a<<<ga, 256>>>(nullptr);     // g_ctx
    split_wT<<<gw, 256>>>(Wo);
    gemm_tc<<<gg, 256, GEMM_SMEM>>>(bo, out, 3, 0);
}

// round 4
// speedup vs baseline: 2.7547x; 2.1017x over previous
#include <cuda_runtime.h>
#include <cuda_bf16.h>
#include <math.h>
#include <stdint.h>

#define Bb 2
#define Ss 2048
#define Dd 1024
#define Hh 16
#define HDd 64
#define Mm (Bb * Ss)

// ---------------- scratch (device globals; no allocation) ----------------
__device__ __align__(16) __nv_bfloat16 g_ah[Mm * Dd];
__device__ __align__(16) __nv_bfloat16 g_al[Mm * Dd];
__device__ __align__(16) __nv_bfloat16 g_bh[Dd * Dd];
__device__ __align__(16) __nv_bfloat16 g_bl[Dd * Dd];
__device__ __align__(16) __nv_bfloat16 g_qh[Bb * Hh * Ss * HDd];
__device__ __align__(16) __nv_bfloat16 g_ql[Bb * Hh * Ss * HDd];
__device__ __align__(16) __nv_bfloat16 g_kh[Bb * Hh * Ss * HDd];
__device__ __align__(16) __nv_bfloat16 g_kl[Bb * Hh * Ss * HDd];
__device__ __align__(16) __nv_bfloat16 g_vh[Bb * Hh * Ss * HDd];
__device__ __align__(16) __nv_bfloat16 g_vl[Bb * Hh * Ss * HDd];

// ---------------- helpers ----------------
static __device__ __forceinline__ uint32_t s2u(const void* p) {
    uint32_t a;
    asm("{ .reg .u64 t; cvta.to.shared.u64 t, %1; cvt.u32.u64 %0, t; }"
        : "=r"(a) : "l"(p));
    return a;
}
static __device__ __forceinline__ float ex2(float x) {
    float y;
    asm("ex2.approx.ftz.f32 %0, %1;" : "=f"(y) : "f"(x));
    return y;
}
static __device__ __forceinline__ uint32_t packbf(float lo, float hi) {
    uint32_t d;
    asm("cvt.rn.bf16x2.f32 %0, %1, %2;" : "=r"(d) : "f"(hi), "f"(lo));
    return d;
}
// split pair of f32 into bf16x2 hi + bf16x2 residual
static __device__ __forceinline__ void split2(float x0, float x1,
                                              uint32_t& h, uint32_t& l) {
    h = packbf(x0, x1);
    float h0 = __uint_as_float(h << 16);
    float h1 = __uint_as_float(h & 0xffff0000u);
    l = packbf(x0 - h0, x1 - h1);
}

#define LDSM_X4(R, addr)                                                        \
    asm volatile("ldmatrix.sync.aligned.m8n8.x4.shared.b16 {%0,%1,%2,%3}, [%4];"\
        : "=r"((R)[0]), "=r"((R)[1]), "=r"((R)[2]), "=r"((R)[3]) : "r"(addr))
#define LDSM_X4_T(R, addr)                                                      \
    asm volatile("ldmatrix.sync.aligned.m8n8.x4.trans.shared.b16 {%0,%1,%2,%3}, [%4];"\
        : "=r"((R)[0]), "=r"((R)[1]), "=r"((R)[2]), "=r"((R)[3]) : "r"(addr))

static __device__ __forceinline__ void mma_bf16(
    float* c, const uint32_t* a, const uint32_t* b)
{
    asm volatile(
        "mma.sync.aligned.m16n8k16.row.col.f32.bf16.bf16.f32 "
        "{%0,%1,%2,%3}, {%4,%5,%6,%7}, {%8,%9}, {%0,%1,%2,%3};"
        : "+f"(c[0]), "+f"(c[1]), "+f"(c[2]), "+f"(c[3])
        : "r"(a[0]), "r"(a[1]), "r"(a[2]), "r"(a[3]), "r"(b[0]), "r"(b[1]));
}

// ---------------- split kernels (fp32 -> bf16 hi/lo) ----------------
__global__ __launch_bounds__(256) void split_a(const float* __restrict__ A)
{
    int i = (blockIdx.x * 256 + threadIdx.x) * 4;
    float4 v = *(const float4*)(A + i);
    uint32_t h0, l0, h1, l1;
    split2(v.x, v.y, h0, l0);
    split2(v.z, v.w, h1, l1);
    *(uint2*)(g_ah + i) = make_uint2(h0, h1);
    *(uint2*)(g_al + i) = make_uint2(l0, l1);
}

// W[K,N] fp32 -> bh/bl[N,K] bf16 (transposed)
__global__ __launch_bounds__(256) void split_wT(const float* __restrict__ W)
{
    __shared__ float t[32][33];
    int n0 = blockIdx.x * 32, k0 = blockIdx.y * 32;
    int tx = threadIdx.x & 31, ty = threadIdx.x >> 5;
#pragma unroll
    for (int r = ty; r < 32; r += 8)
        t[r][tx] = W[(size_t)(k0 + r) * Dd + n0 + tx];
    __syncthreads();
#pragma unroll
    for (int r = ty; r < 32; r += 8) {
        float x = t[tx][r];
        __nv_bfloat16 h = __float2bfloat16(x);
        __nv_bfloat16 l = __float2bfloat16(x - __bfloat162float(h));
        size_t o = (size_t)(n0 + r) * Dd + k0 + tx;
        g_bh[o] = h;
        g_bl[o] = l;
    }
}

// ---------------- mma.sync GEMM: C[M,N] = A*W + bias ----------------
#define GBM 128
#define GBN 128
#define GBK 32
#define TILEB (128 * 40 * 2)        // 10240 bytes per tile (80B padded rows)
#define STAGEB (4 * TILEB)
#define GEMM_SMEM (2 * STAGEB)      // 81920

__global__ __launch_bounds__(256) void gemm_tc(
    const float* __restrict__ bias, float* __restrict__ Cext, int dst, int split)
{
    extern __shared__ char smem[];
    const int tid = threadIdx.x, wid = tid >> 5, lane = tid & 31;
    const int warpM = wid & 3, warpN = wid >> 2;
    const int brow = blockIdx.y * GBM, bcol = blockIdx.x * GBN;
    const uint32_t sb = s2u(smem);

    float acc[2][8][4];
#pragma unroll
    for (int mf = 0; mf < 2; mf++)
#pragma unroll
        for (int nf = 0; nf < 8; nf++)
#pragma unroll
            for (int q = 0; q < 4; q++) acc[mf][nf][q] = 0.0f;

    const int t = tid >> 6;
    const __nv_bfloat16* src = (t == 0) ? g_ah : (t == 1) ? g_al
                             : (t == 2) ? g_bh : g_bl;
    const int rb = (t < 2) ? brow : bcol;
    const int lbase = tid & 63;

#define LOAD_CHUNK(c) do {                                                     \
    int k0_ = (c) * GBK;                                                       \
    uint32_t st_ = sb + ((c) & 1) * STAGEB + t * TILEB;                        \
    _Pragma("unroll")                                                          \
    for (int i_ = 0; i_ < 8; i_++) {                                           \
        int idx_ = lbase + i_ * 64;                                            \
        int row_ = idx_ >> 2, cc_ = idx_ & 3;                                  \
        const void* g_ = src + (size_t)(rb + row_) * Dd + k0_ + cc_ * 8;       \
        uint32_t s_ = st_ + row_ * 80 + cc_ * 16;                              \
        asm volatile("cp.async.cg.shared.global [%0], [%1], 16;"               \
                     :: "r"(s_), "l"(g_));                                     \
    }                                                                          \
    asm volatile("cp.async.commit_group;");                                    \
} while (0)

    LOAD_CHUNK(0);

    const int NKC = Dd / GBK;
    for (int c = 0; c < NKC; c++) {
        if (c + 1 < NKC) {
            LOAD_CHUNK(c + 1);
            asm volatile("cp.async.wait_group 1;");
        } else {
            asm volatile("cp.async.wait_group 0;");
        }
        __syncthreads();

        const uint32_t stage = sb + (c & 1) * STAGEB;
        const int arow = warpM * 32 + (lane & 15);
        const int acolb = ((lane >> 4) & 1) * 16;
        const int bn = warpN * 64 + (lane & 7) + ((lane & 16) ? 8 : 0);
        const int bkb = ((lane & 8) ? 16 : 0);

#pragma unroll
        for (int ks = 0; ks < 2; ks++) {
            const int kb = ks * 32;
            uint32_t ah[2][4], al[2][4], bh2[4][4], bl2[4][4];
#pragma unroll
            for (int mf = 0; mf < 2; mf++) {
                uint32_t ad = stage + (arow + mf * 16) * 80 + kb + acolb;
                LDSM_X4(ah[mf], ad);
                LDSM_X4(al[mf], ad + TILEB);
            }
#pragma unroll
            for (int nb = 0; nb < 4; nb++) {
                uint32_t bd = stage + 2 * TILEB + (bn + nb * 16) * 80 + kb + bkb;
                LDSM_X4(bh2[nb], bd);
                LDSM_X4(bl2[nb], bd + TILEB);
            }
#pragma unroll
            for (int mf = 0; mf < 2; mf++)
#pragma unroll
                for (int nf = 0; nf < 8; nf++) {
                    const uint32_t* bhp = &bh2[nf >> 1][(nf & 1) * 2];
                    const uint32_t* blp = &bl2[nf >> 1][(nf & 1) * 2];
                    mma_bf16(acc[mf][nf], ah[mf], bhp);
                    mma_bf16(acc[mf][nf], al[mf], bhp);
                    mma_bf16(acc[mf][nf], ah[mf], blp);
                }
        }
        __syncthreads();
    }

    // epilogue
    if (split) {
        __nv_bfloat16* Ch = (dst == 0) ? g_qh : (dst == 1) ? g_kh : g_vh;
        __nv_bfloat16* Cl = (dst == 0) ? g_ql : (dst == 1) ? g_kl : g_vl;
#pragma unroll
        for (int mf = 0; mf < 2; mf++) {
            int r0 = brow + warpM * 32 + mf * 16 + (lane >> 2);
#pragma unroll
            for (int nf = 0; nf < 8; nf++) {
                int col = bcol + warpN * 64 + nf * 8 + (lane & 3) * 2;
                float bx = bias[col], by = bias[col + 1];
                int h = col >> 6, hd = col & 63;
                uint32_t ph, pl;
                split2(acc[mf][nf][0] + bx, acc[mf][nf][1] + by, ph, pl);
                int b0 = r0 >> 11, s0 = r0 & 2047;
                size_t o0 = (((size_t)b0 * Hh + h) * Ss + s0) * HDd + hd;
                *(uint32_t*)&Ch[o0] = ph;
                *(uint32_t*)&Cl[o0] = pl;
                split2(acc[mf][nf][2] + bx, acc[mf][nf][3] + by, ph, pl);
                int r1 = r0 + 8;
                int b1 = r1 >> 11, s1 = r1 & 2047;
                size_t o1 = (((size_t)b1 * Hh + h) * Ss + s1) * HDd + hd;
                *(uint32_t*)&Ch[o1] = ph;
                *(uint32_t*)&Cl[o1] = pl;
            }
        }
    } else {
#pragma unroll
        for (int mf = 0; mf < 2; mf++) {
            int r0 = brow + warpM * 32 + mf * 16 + (lane >> 2);
#pragma unroll
            for (int nf = 0; nf < 8; nf++) {
                int col = bcol + warpN * 64 + nf * 8 + (lane & 3) * 2;
                float bx = bias[col], by = bias[col + 1];
                float2 v0 = make_float2(acc[mf][nf][0] + bx, acc[mf][nf][1] + by);
                float2 v1 = make_float2(acc[mf][nf][2] + bx, acc[mf][nf][3] + by);
                *(float2*)&Cext[(size_t)r0 * Dd + col] = v0;
                *(float2*)&Cext[(size_t)(r0 + 8) * Dd + col] = v1;
            }
        }
    }
}

// ---------------- causal flash attention on tensor cores ----------------
// CTA: 128 threads (4 warps), tile 64 q-rows x 64 kv. Warp w owns q rows
// [w*16, w*16+16). Hi/lo 3-pass mma for both S=QK^T and P@V. Online softmax
// in registers (quad shfl reductions). Output written as bf16 hi/lo straight
// into g_ah/g_al (A operand of the final projection).
#define FTILE 9216                  // 64 rows * 144B (128B data + 16B pad)
#define FSTAGE (4 * FTILE)          // kh, kl, vh, vl
#define FQH 0
#define FQL FTILE
#define FSTG (2 * FTILE)
#define FLASH_SMEM (FSTG + 2 * FSTAGE)   // 92160
#define SCALE_L2E (0.03125f * 1.4426950408889634f)

__global__ __launch_bounds__(128) void flash_mma()
{
    extern __shared__ char sm[];
    const uint32_t sb = s2u(sm);
    const int tid = threadIdx.x, wid = tid >> 5, lane = tid & 31;
    const int qtile = (Ss / 64 - 1) - blockIdx.x;   // heavy tiles first
    const int bhid = blockIdx.y;

    const __nv_bfloat16* qhp = g_qh + ((size_t)bhid * Ss + qtile * 64) * HDd;
    const __nv_bfloat16* qlp = g_ql + ((size_t)bhid * Ss + qtile * 64) * HDd;
    const __nv_bfloat16* khp = g_kh + (size_t)bhid * Ss * HDd;
    const __nv_bfloat16* klp = g_kl + (size_t)bhid * Ss * HDd;
    const __nv_bfloat16* vhp = g_vh + (size_t)bhid * Ss * HDd;
    const __nv_bfloat16* vlp = g_vl + (size_t)bhid * Ss * HDd;

    // load Q tile (hi+lo) into smem
#pragma unroll
    for (int i = 0; i < 4; i++) {
        int idx = tid + i * 128, row = idx >> 3, ch = idx & 7;
        *(uint4*)(sm + FQH + row * 144 + ch * 16) = *(const uint4*)(qhp + row * HDd + ch * 8);
        *(uint4*)(sm + FQL + row * 144 + ch * 16) = *(const uint4*)(qlp + row * HDd + ch * 8);
    }

#define KVLOAD(jj, buf) do {                                                   \
    int br_ = (jj) * 64;                                                       \
    _Pragma("unroll")                                                          \
    for (int t_ = 0; t_ < 4; t_++) {                                           \
        const __nv_bfloat16* s_ = (t_ == 0) ? khp : (t_ == 1) ? klp            \
                                : (t_ == 2) ? vhp : vlp;                       \
        _Pragma("unroll")                                                      \
        for (int i_ = 0; i_ < 4; i_++) {                                       \
            int idx_ = tid + i_ * 128;                                         \
            int row_ = idx_ >> 3, ch_ = idx_ & 7;                              \
            uint32_t d_ = sb + FSTG + (buf) * FSTAGE + t_ * FTILE              \
                        + row_ * 144 + ch_ * 16;                               \
            const void* g_ = s_ + (size_t)(br_ + row_) * HDd + ch_ * 8;        \
            asm volatile("cp.async.cg.shared.global [%0], [%1], 16;"           \
                         :: "r"(d_), "l"(g_));                                 \
        }                                                                      \
    }                                                                          \
    asm volatile("cp.async.commit_group;");                                    \
} while (0)

    KVLOAD(0, 0);

    float oacc[8][4];
#pragma unroll
    for (int nt = 0; nt < 8; nt++)
#pragma unroll
        for (int q = 0; q < 4; q++) oacc[nt][q] = 0.0f;
    float rowm0 = -1e30f, rowm1 = -1e30f, rowl0 = 0.0f, rowl1 = 0.0f;

    const int wm = wid;
    const uint32_t a_addr = sb + (wm * 16 + (lane & 15)) * 144 + ((lane >> 4) & 1) * 16;
    const int krow = (lane & 7) + ((lane & 16) ? 8 : 0);
    const int kkb = (lane & 8) ? 16 : 0;
    const int vrow = (lane & 15);
    const int vcb = ((lane >> 4) & 1) * 16;
    const int rrel0 = wm * 16 + (lane >> 2);       // CTA-relative q row
    const int rrel1 = rrel0 + 8;

    for (int j = 0; j <= qtile; j++) {
        if (j < qtile) {
            KVLOAD(j + 1, (j + 1) & 1);
            asm volatile("cp.async.wait_group 1;");
        } else {
            asm volatile("cp.async.wait_group 0;");
        }
        __syncthreads();

        const uint32_t stage = sb + FSTG + (j & 1) * FSTAGE;

        // ---- S = Q K^T (3-pass hi/lo) ----
        float sacc[8][4];
#pragma unroll
        for (int nt = 0; nt < 8; nt++)
#pragma unroll
            for (int q = 0; q < 4; q++) sacc[nt][q] = 0.0f;

#pragma unroll
        for (int ks = 0; ks < 4; ks++) {
            uint32_t aqh[4], aql[4];
            LDSM_X4(aqh, a_addr + FQH + ks * 32);
            LDSM_X4(aql, a_addr + FQL + ks * 32);
#pragma unroll
            for (int nt16 = 0; nt16 < 4; nt16++) {
                uint32_t kbh[4], kbl[4];
                uint32_t bd = stage + (krow + nt16 * 16) * 144 + kkb + ks * 32;
                LDSM_X4(kbh, bd);
                LDSM_X4(kbl, bd + FTILE);
                mma_bf16(sacc[2 * nt16], aqh, &kbh[0]);
                mma_bf16(sacc[2 * nt16], aql, &kbh[0]);
                mma_bf16(sacc[2 * nt16], aqh, &kbl[0]);
                mma_bf16(sacc[2 * nt16 + 1], aqh, &kbh[2]);
                mma_bf16(sacc[2 * nt16 + 1], aql, &kbh[2]);
                mma_bf16(sacc[2 * nt16 + 1], aqh, &kbl[2]);
            }
        }

        // ---- scale + causal mask + online softmax (registers) ----
        const bool diag = (j == qtile);
        float mx0 = -1e30f, mx1 = -1e30f;
#pragma unroll
        for (int nt = 0; nt < 8; nt++) {
            float t0 = sacc[nt][0] * SCALE_L2E;
            float t1 = sacc[nt][1] * SCALE_L2E;
            float t2 = sacc[nt][2] * SCALE_L2E;
            float t3 = sacc[nt][3] * SCALE_L2E;
            if (diag) {
                int c0 = nt * 8 + 2 * (lane & 3);
                if (c0 > rrel0) t0 = -1e30f;
                if (c0 + 1 > rrel0) t1 = -1e30f;
                if (c0 > rrel1) t2 = -1e30f;
                if (c0 + 1 > rrel1) t3 = -1e30f;
            }
            sacc[nt][0] = t0; sacc[nt][1] = t1;
            sacc[nt][2] = t2; sacc[nt][3] = t3;
            mx0 = fmaxf(mx0, fmaxf(t0, t1));
            mx1 = fmaxf(mx1, fmaxf(t2, t3));
        }
        mx0 = fmaxf(mx0, __shfl_xor_sync(0xffffffffu, mx0, 1));
        mx0 = fmaxf(mx0, __shfl_xor_sync(0xffffffffu, mx0, 2));
        mx1 = fmaxf(mx1, __shfl_xor_sync(0xffffffffu, mx1, 1));
        mx1 = fmaxf(mx1, __shfl_xor_sync(0xffffffffu, mx1, 2));
        float mnew0 = fmaxf(rowm0, mx0);
        float mnew1 = fmaxf(rowm1, mx1);
        float a0 = ex2(rowm0 - mnew0);
        float a1 = ex2(rowm1 - mnew1);
        float sum0 = 0.0f, sum1 = 0.0f;
#pragma unroll
        for (int nt = 0; nt < 8; nt++) {
            float p0 = ex2(sacc[nt][0] - mnew0);
            float p1 = ex2(sacc[nt][1] - mnew0);
            float p2 = ex2(sacc[nt][2] - mnew1);
            float p3 = ex2(sacc[nt][3] - mnew1);
            sacc[nt][0] = p0; sacc[nt][1] = p1;
            sacc[nt][2] = p2; sacc[nt][3] = p3;
            sum0 += p0 + p1;
            sum1 += p2 + p3;
        }
        sum0 += __shfl_xor_sync(0xffffffffu, sum0, 1);
        sum0 += __shfl_xor_sync(0xffffffffu, sum0, 2);
        sum1 += __shfl_xor_sync(0xffffffffu, sum1, 1);
        sum1 += __shfl_xor_sync(0xffffffffu, sum1, 2);
        rowl0 = rowl0 * a0 + sum0;
        rowl1 = rowl1 * a1 + sum1;
        rowm0 = mnew0;
        rowm1 = mnew1;
#pragma unroll
        for (int nt = 0; nt < 8; nt++) {
            oacc[nt][0] *= a0; oacc[nt][1] *= a0;
            oacc[nt][2] *= a1; oacc[nt][3] *= a1;
        }

        // ---- O += P V (3-pass hi/lo; P fragments reused from sacc) ----
#pragma unroll
        for (int ks2 = 0; ks2 < 4; ks2++) {
            uint32_t aph[4], apl[4];
            split2(sacc[2 * ks2][0], sacc[2 * ks2][1], aph[0], apl[0]);
            split2(sacc[2 * ks2][2], sacc[2 * ks2][3], aph[1], apl[1]);
            split2(sacc[2 * ks2 + 1][0], sacc[2 * ks2 + 1][1], aph[2], apl[2]);
            split2(sacc[2 * ks2 + 1][2], sacc[2 * ks2 + 1][3], aph[3], apl[3]);
#pragma unroll
            for (int nt16 = 0; nt16 < 4; nt16++) {
                uint32_t vbh[4], vbl[4];
                uint32_t vd = stage + 2 * FTILE + (ks2 * 16 + vrow) * 144
                            + nt16 * 32 + vcb;
                LDSM_X4_T(vbh, vd);
                LDSM_X4_T(vbl, vd + FTILE);
                mma_bf16(oacc[2 * nt16], aph, &vbh[0]);
                mma_bf16(oacc[2 * nt16], apl, &vbh[0]);
                mma_bf16(oacc[2 * nt16], aph, &vbl[0]);
                mma_bf16(oacc[2 * nt16 + 1], aph, &vbh[2]);
                mma_bf16(oacc[2 * nt16 + 1], apl, &vbh[2]);
                mma_bf16(oacc[2 * nt16 + 1], aph, &vbl[2]);
            }
        }
        __syncthreads();   // protect stage buffer before next prefetch
    }

    // ---- epilogue: normalize, write bf16 hi/lo into g_ah/g_al ----
    float inv0 = 1.0f / rowl0;
    float inv1 = 1.0f / rowl1;
    int b = bhid >> 4, h = bhid & 15;
    int row0 = b * Ss + qtile * 64 + rrel0;
    int row1 = row0 + 8;
#pragma unroll
    for (int nt = 0; nt < 8; nt++) {
        int col = h * 64 + nt * 8 + 2 * (lane & 3);
        uint32_t ph, pl;
        split2(oacc[nt][0] * inv0, oacc[nt][1] * inv0, ph, pl);
        *(uint32_t*)&g_ah[(size_t)row0 * Dd + col] = ph;
        *(uint32_t*)&g_al[(size_t)row0 * Dd + col] = pl;
        split2(oacc[nt][2] * inv1, oacc[nt][3] * inv1, ph, pl);
        *(uint32_t*)&g_ah[(size_t)row1 * Dd + col] = ph;
        *(uint32_t*)&g_al[(size_t)row1 * Dd + col] = pl;
    }
}

// ---------------- launch ----------------
// Input order: K, V, Q, mask, Wk, bk, Wv, bv, Wq, bq, Wo, bo
extern "C" void kernel_launch(void* const* d_in, const int* in_sizes, int n_in,
                              void* d_out, int out_size)
{
    const float* K  = (const float*)d_in[0];
    const float* V  = (const float*)d_in[1];
    const float* Q  = (const float*)d_in[2];
    const float* Wk = (const float*)d_in[4];
    const float* bk = (const float*)d_in[5];
    const float* Wv = (const float*)d_in[6];
    const float* bv = (const float*)d_in[7];
    const float* Wq = (const float*)d_in[8];
    const float* bq = (const float*)d_in[9];
    const float* Wo = (const float*)d_in[10];
    const float* bo = (const float*)d_in[11];
    float* out = (float*)d_out;

    cudaFuncSetAttribute(gemm_tc, cudaFuncAttributeMaxDynamicSharedMemorySize, GEMM_SMEM);
    cudaFuncSetAttribute(flash_mma, cudaFuncAttributeMaxDynamicSharedMemorySize, FLASH_SMEM);

    dim3 gg(Dd / GBN, Mm / GBM);       // (8, 32)
    dim3 gw(Dd / 32, Dd / 32);         // (32, 32)
    int  ga = (Mm * Dd) / (256 * 4);   // 4096

    split_a<<<ga, 256>>>(Q);
    split_wT<<<gw, 256>>>(Wq);
    gemm_tc<<<gg, 256, GEMM_SMEM>>>(bq, nullptr, 0, 1);

    split_a<<<ga, 256>>>(K);
    split_wT<<<gw, 256>>>(Wk);
    gemm_tc<<<gg, 256, GEMM_SMEM>>>(bk, nullptr, 1, 1);

    split_a<<<ga, 256>>>(V);
    split_wT<<<gw, 256>>>(Wv);
    gemm_tc<<<gg, 256, GEMM_SMEM>>>(bv, nullptr, 2, 1);

    flash_mma<<<dim3(Ss / 64, Bb * Hh), 128, FLASH_SMEM>>>();

    split_wT<<<gw, 256>>>(Wo);
    gemm_tc<<<gg, 256, GEMM_SMEM>>>(bo, out, 3, 0);
}

// round 5
// speedup vs baseline: 4.3356x; 1.5739x over previous
#include <cuda_runtime.h>
#include <cuda_fp16.h>
#include <math.h>
#include <stdint.h>

#define Bb 2
#define Ss 2048
#define Dd 1024
#define Hh 16
#define HDd 64
#define Mm (Bb * Ss)
#define SLICE (Mm * Dd)

// ---------------- scratch (device globals; no allocation) ----------------
__device__ __align__(16) __half g_ah[3 * SLICE];      // A hi: slices Q,K,V / ctx in 0
__device__ __align__(16) __half g_al[3 * SLICE];      // A lo
__device__ __align__(16) __half g_bh[4 * Dd * Dd];    // W hi, transposed [N,K]: Wq,Wk,Wv,Wo
__device__ __align__(16) __half g_qh[Bb * Hh * Ss * HDd];
__device__ __align__(16) __half g_ql[Bb * Hh * Ss * HDd];
__device__ __align__(16) __half g_kh[Bb * Hh * Ss * HDd];
__device__ __align__(16) __half g_vh[Bb * Hh * Ss * HDd];

// ---------------- helpers ----------------
static __device__ __forceinline__ uint32_t s2u(const void* p) {
    uint32_t a;
    asm("{ .reg .u64 t; cvta.to.shared.u64 t, %1; cvt.u32.u64 %0, t; }"
        : "=r"(a) : "l"(p));
    return a;
}
static __device__ __forceinline__ float ex2(float x) {
    float y;
    asm("ex2.approx.ftz.f32 %0, %1;" : "=f"(y) : "f"(x));
    return y;
}
static __device__ __forceinline__ uint32_t packh2(float lo, float hi) {
    uint32_t d;
    asm("cvt.rn.f16x2.f32 %0, %1, %2;" : "=r"(d) : "f"(hi), "f"(lo));
    return d;
}
// split pair of f32 into f16x2 hi + f16x2 residual
static __device__ __forceinline__ void split2h(float x0, float x1,
                                               uint32_t& h, uint32_t& l) {
    h = packh2(x0, x1);
    float2 hf = __half22float2(*(__half2*)&h);
    l = packh2(x0 - hf.x, x1 - hf.y);
}

#define LDSM_X4(R, addr)                                                        \
    asm volatile("ldmatrix.sync.aligned.m8n8.x4.shared.b16 {%0,%1,%2,%3}, [%4];"\
        : "=r"((R)[0]), "=r"((R)[1]), "=r"((R)[2]), "=r"((R)[3]) : "r"(addr))
#define LDSM_X4_T(R, addr)                                                      \
    asm volatile("ldmatrix.sync.aligned.m8n8.x4.trans.shared.b16 {%0,%1,%2,%3}, [%4];"\
        : "=r"((R)[0]), "=r"((R)[1]), "=r"((R)[2]), "=r"((R)[3]) : "r"(addr))

static __device__ __forceinline__ void mma_f16(
    float* c, const uint32_t* a, const uint32_t* b)
{
    asm volatile(
        "mma.sync.aligned.m16n8k16.row.col.f32.f16.f16.f32 "
        "{%0,%1,%2,%3}, {%4,%5,%6,%7}, {%8,%9}, {%0,%1,%2,%3};"
        : "+f"(c[0]), "+f"(c[1]), "+f"(c[2]), "+f"(c[3])
        : "r"(a[0]), "r"(a[1]), "r"(a[2]), "r"(a[3]), "r"(b[0]), "r"(b[1]));
}

// ---------------- split kernels ----------------
// Inputs Q,K,V (fp32) -> A slices hi/lo fp16. grid (4096, 3)
__global__ __launch_bounds__(256) void split_qkv(
    const float* __restrict__ Q, const float* __restrict__ K,
    const float* __restrict__ V)
{
    int z = blockIdx.y;
    const float* A = (z == 0) ? Q : (z == 1) ? K : V;
    int i = (blockIdx.x * 256 + threadIdx.x) * 4;
    float4 v = *(const float4*)(A + i);
    uint32_t h0, l0, h1, l1;
    split2h(v.x, v.y, h0, l0);
    split2h(v.z, v.w, h1, l1);
    *(uint2*)(g_ah + z * SLICE + i) = make_uint2(h0, h1);
    *(uint2*)(g_al + z * SLICE + i) = make_uint2(l0, l1);
}

// W[K,N] fp32 -> g_bh slice [N,K] fp16 (transposed, hi only). grid (32,32,4)
__global__ __launch_bounds__(256) void split_w(
    const float* __restrict__ Wq, const float* __restrict__ Wk,
    const float* __restrict__ Wv, const float* __restrict__ Wo)
{
    __shared__ float t[32][33];
    int z = blockIdx.z;
    const float* W = (z == 0) ? Wq : (z == 1) ? Wk : (z == 2) ? Wv : Wo;
    int n0 = blockIdx.x * 32, k0 = blockIdx.y * 32;
    int tx = threadIdx.x & 31, ty = threadIdx.x >> 5;
#pragma unroll
    for (int r = ty; r < 32; r += 8)
        t[r][tx] = W[(size_t)(k0 + r) * Dd + n0 + tx];
    __syncthreads();
#pragma unroll
    for (int r = ty; r < 32; r += 8)
        g_bh[(size_t)z * Dd * Dd + (size_t)(n0 + r) * Dd + k0 + tx] =
            __float2half(t[tx][r]);
}

// ---------------- mma.sync GEMM core (fp16, 2-pass) ----------------
#define GBM 128
#define GBN 128
#define GBK 32
#define TILEB (128 * 40 * 2)        // 10240 B per tile (80B padded rows)
#define STAGEB (3 * TILEB)          // ah, al, bh
#define GEMM_SMEM (2 * STAGEB)      // 61440

static __device__ __forceinline__ void gemm_core(
    const __half* __restrict__ Ah, const __half* __restrict__ Al,
    const __half* __restrict__ Bh, uint32_t sb,
    int brow, int bcol, float acc[2][8][4])
{
    const int tid = threadIdx.x, wid = tid >> 5, lane = tid & 31;
    const int warpM = wid & 3, warpN = wid >> 2;

#pragma unroll
    for (int mf = 0; mf < 2; mf++)
#pragma unroll
        for (int nf = 0; nf < 8; nf++)
#pragma unroll
            for (int q = 0; q < 4; q++) acc[mf][nf][q] = 0.0f;

#define LOAD_CHUNK(c) do {                                                     \
    int k0_ = (c) * GBK;                                                       \
    uint32_t st_ = sb + ((c) & 1) * STAGEB;                                    \
    _Pragma("unroll")                                                          \
    for (int i_ = 0; i_ < 6; i_++) {                                           \
        int idx_ = tid + i_ * 256;                                             \
        int t_ = idx_ >> 9, w_ = idx_ & 511;                                   \
        int row_ = w_ >> 2, cc_ = w_ & 3;                                      \
        const __half* s_ = (t_ == 0) ? Ah : (t_ == 1) ? Al : Bh;               \
        int rb_ = (t_ < 2) ? brow : bcol;                                      \
        const void* g_ = s_ + (size_t)(rb_ + row_) * Dd + k0_ + cc_ * 8;       \
        uint32_t d_ = st_ + t_ * TILEB + row_ * 80 + cc_ * 16;                 \
        asm volatile("cp.async.cg.shared.global [%0], [%1], 16;"               \
                     :: "r"(d_), "l"(g_));                                     \
    }                                                                          \
    asm volatile("cp.async.commit_group;");                                    \
} while (0)

    LOAD_CHUNK(0);

    const int NKC = Dd / GBK;
    for (int c = 0; c < NKC; c++) {
        if (c + 1 < NKC) {
            LOAD_CHUNK(c + 1);
            asm volatile("cp.async.wait_group 1;");
        } else {
            asm volatile("cp.async.wait_group 0;");
        }
        __syncthreads();

        const uint32_t stage = sb + (c & 1) * STAGEB;
        const int arow = warpM * 32 + (lane & 15);
        const int acolb = ((lane >> 4) & 1) * 16;
        const int bn = warpN * 64 + (lane & 7) + ((lane & 16) ? 8 : 0);
        const int bkb = ((lane & 8) ? 16 : 0);

#pragma unroll
        for (int ks = 0; ks < 2; ks++) {
            const int kb = ks * 32;
            uint32_t ah[2][4], al[2][4], bh2[4][4];
#pragma unroll
            for (int mf = 0; mf < 2; mf++) {
                uint32_t ad = stage + (arow + mf * 16) * 80 + kb + acolb;
                LDSM_X4(ah[mf], ad);
                LDSM_X4(al[mf], ad + TILEB);
            }
#pragma unroll
            for (int nb = 0; nb < 4; nb++) {
                uint32_t bd = stage + 2 * TILEB + (bn + nb * 16) * 80 + kb + bkb;
                LDSM_X4(bh2[nb], bd);
            }
#pragma unroll
            for (int mf = 0; mf < 2; mf++)
#pragma unroll
                for (int nf = 0; nf < 8; nf++) {
                    const uint32_t* bhp = &bh2[nf >> 1][(nf & 1) * 2];
                    mma_f16(acc[mf][nf], ah[mf], bhp);
                    mma_f16(acc[mf][nf], al[mf], bhp);
                }
        }
        __syncthreads();
    }
#undef LOAD_CHUNK
}

// QKV projections fused: grid (8, 32, 3)
__global__ __launch_bounds__(256) void gemm_qkv(
    const float* __restrict__ bq, const float* __restrict__ bk,
    const float* __restrict__ bv)
{
    extern __shared__ char smem[];
    const int z = blockIdx.z;
    const int brow = blockIdx.y * GBM, bcol = blockIdx.x * GBN;
    const float* bias = (z == 0) ? bq : (z == 1) ? bk : bv;

    float acc[2][8][4];
    gemm_core(g_ah + (size_t)z * SLICE, g_al + (size_t)z * SLICE,
              g_bh + (size_t)z * Dd * Dd, s2u(smem), brow, bcol, acc);

    const int tid = threadIdx.x, wid = tid >> 5, lane = tid & 31;
    const int warpM = wid & 3, warpN = wid >> 2;
#pragma unroll
    for (int mf = 0; mf < 2; mf++) {
        int r0 = brow + warpM * 32 + mf * 16 + (lane >> 2);
#pragma unroll
        for (int nf = 0; nf < 8; nf++) {
            int col = bcol + warpN * 64 + nf * 8 + (lane & 3) * 2;
            float bx = bias[col], by = bias[col + 1];
            int h = col >> 6, hd = col & 63;
            float v00 = acc[mf][nf][0] + bx, v01 = acc[mf][nf][1] + by;
            float v10 = acc[mf][nf][2] + bx, v11 = acc[mf][nf][3] + by;
            int r1 = r0 + 8;
            size_t o0 = (((size_t)(r0 >> 11) * Hh + h) * Ss + (r0 & 2047)) * HDd + hd;
            size_t o1 = (((size_t)(r1 >> 11) * Hh + h) * Ss + (r1 & 2047)) * HDd + hd;
            if (z == 0) {       // Q: hi/lo split
                uint32_t ph, pl;
                split2h(v00, v01, ph, pl);
                *(uint32_t*)&g_qh[o0] = ph;
                *(uint32_t*)&g_ql[o0] = pl;
                split2h(v10, v11, ph, pl);
                *(uint32_t*)&g_qh[o1] = ph;
                *(uint32_t*)&g_ql[o1] = pl;
            } else {            // K/V: single fp16
                __half* C = (z == 1) ? g_kh : g_vh;
                *(uint32_t*)&C[o0] = packh2(v00, v01);
                *(uint32_t*)&C[o1] = packh2(v10, v11);
            }
        }
    }
}

// Output projection: grid (8, 32)
__global__ __launch_bounds__(256) void gemm_out(
    const float* __restrict__ bias, float* __restrict__ Cext)
{
    extern __shared__ char smem[];
    const int brow = blockIdx.y * GBM, bcol = blockIdx.x * GBN;

    float acc[2][8][4];
    gemm_core(g_ah, g_al, g_bh + (size_t)3 * Dd * Dd, s2u(smem), brow, bcol, acc);

    const int tid = threadIdx.x, wid = tid >> 5, lane = tid & 31;
    const int warpM = wid & 3, warpN = wid >> 2;
#pragma unroll
    for (int mf = 0; mf < 2; mf++) {
        int r0 = brow + warpM * 32 + mf * 16 + (lane >> 2);
#pragma unroll
        for (int nf = 0; nf < 8; nf++) {
            int col = bcol + warpN * 64 + nf * 8 + (lane & 3) * 2;
            float bx = bias[col], by = bias[col + 1];
            float2 v0 = make_float2(acc[mf][nf][0] + bx, acc[mf][nf][1] + by);
            float2 v1 = make_float2(acc[mf][nf][2] + bx, acc[mf][nf][3] + by);
            *(float2*)&Cext[(size_t)r0 * Dd + col] = v0;
            *(float2*)&Cext[(size_t)(r0 + 8) * Dd + col] = v1;
        }
    }
}

// ---------------- causal flash attention on tensor cores (fp16 2-pass) ----
#define FTILE 9216                  // 64 rows * 144B (128B data + 16B pad)
#define FSTAGE (2 * FTILE)          // kh, vh
#define FQH 0
#define FQL FTILE
#define FSTG (2 * FTILE)
#define FLASH_SMEM (FSTG + 2 * FSTAGE)   // 55296
#define SCALE_L2E (0.03125f * 1.4426950408889634f)

__global__ __launch_bounds__(128) void flash_mma()
{
    extern __shared__ char sm[];
    const uint32_t sb = s2u(sm);
    const int tid = threadIdx.x, wid = tid >> 5, lane = tid & 31;
    const int qtile = (Ss / 64 - 1) - blockIdx.x;   // heavy tiles first
    const int bhid = blockIdx.y;

    const __half* qhp = g_qh + ((size_t)bhid * Ss + qtile * 64) * HDd;
    const __half* qlp = g_ql + ((size_t)bhid * Ss + qtile * 64) * HDd;
    const __half* khp = g_kh + (size_t)bhid * Ss * HDd;
    const __half* vhp = g_vh + (size_t)bhid * Ss * HDd;

    // load Q tile (hi+lo) into smem
#pragma unroll
    for (int i = 0; i < 4; i++) {
        int idx = tid + i * 128, row = idx >> 3, ch = idx & 7;
        *(uint4*)(sm + FQH + row * 144 + ch * 16) = *(const uint4*)(qhp + row * HDd + ch * 8);
        *(uint4*)(sm + FQL + row * 144 + ch * 16) = *(const uint4*)(qlp + row * HDd + ch * 8);
    }

#define KVLOAD(jj, buf) do {                                                   \
    int br_ = (jj) * 64;                                                       \
    _Pragma("unroll")                                                          \
    for (int t_ = 0; t_ < 2; t_++) {                                           \
        const __half* s_ = (t_ == 0) ? khp : vhp;                              \
        _Pragma("unroll")                                                      \
        for (int i_ = 0; i_ < 4; i_++) {                                       \
            int idx_ = tid + i_ * 128;                                         \
            int row_ = idx_ >> 3, ch_ = idx_ & 7;                              \
            uint32_t d_ = sb + FSTG + (buf) * FSTAGE + t_ * FTILE              \
                        + row_ * 144 + ch_ * 16;                               \
            const void* g_ = s_ + (size_t)(br_ + row_) * HDd + ch_ * 8;        \
            asm volatile("cp.async.cg.shared.global [%0], [%1], 16;"           \
                         :: "r"(d_), "l"(g_));                                 \
        }                                                                      \
    }                                                                          \
    asm volatile("cp.async.commit_group;");                                    \
} while (0)

    KVLOAD(0, 0);

    float oacc[8][4];
#pragma unroll
    for (int nt = 0; nt < 8; nt++)
#pragma unroll
        for (int q = 0; q < 4; q++) oacc[nt][q] = 0.0f;
    float rowm0 = -1e30f, rowm1 = -1e30f, rowl0 = 0.0f, rowl1 = 0.0f;

    const int wm = wid;
    const uint32_t a_addr = sb + (wm * 16 + (lane & 15)) * 144 + ((lane >> 4) & 1) * 16;
    const int krow = (lane & 7) + ((lane & 16) ? 8 : 0);
    const int kkb = (lane & 8) ? 16 : 0;
    const int vrow = (lane & 15);
    const int vcb = ((lane >> 4) & 1) * 16;
    const int rrel0 = wm * 16 + (lane >> 2);
    const int rrel1 = rrel0 + 8;

    for (int j = 0; j <= qtile; j++) {
        if (j < qtile) {
            KVLOAD(j + 1, (j + 1) & 1);
            asm volatile("cp.async.wait_group 1;");
        } else {
            asm volatile("cp.async.wait_group 0;");
        }
        __syncthreads();

        const uint32_t stage = sb + FSTG + (j & 1) * FSTAGE;

        // ---- S = Q K^T (2-pass: qh*kh + ql*kh) ----
        float sacc[8][4];
#pragma unroll
        for (int nt = 0; nt < 8; nt++)
#pragma unroll
            for (int q = 0; q < 4; q++) sacc[nt][q] = 0.0f;

#pragma unroll
        for (int ks = 0; ks < 4; ks++) {
            uint32_t aqh[4], aql[4];
            LDSM_X4(aqh, a_addr + FQH + ks * 32);
            LDSM_X4(aql, a_addr + FQL + ks * 32);
#pragma unroll
            for (int nt16 = 0; nt16 < 4; nt16++) {
                uint32_t kbh[4];
                uint32_t bd = stage + (krow + nt16 * 16) * 144 + kkb + ks * 32;
                LDSM_X4(kbh, bd);
                mma_f16(sacc[2 * nt16], aqh, &kbh[0]);
                mma_f16(sacc[2 * nt16], aql, &kbh[0]);
                mma_f16(sacc[2 * nt16 + 1], aqh, &kbh[2]);
                mma_f16(sacc[2 * nt16 + 1], aql, &kbh[2]);
            }
        }

        // ---- scale + causal mask + online softmax (registers) ----
        const bool diag = (j == qtile);
        float mx0 = -1e30f, mx1 = -1e30f;
#pragma unroll
        for (int nt = 0; nt < 8; nt++) {
            float t0 = sacc[nt][0] * SCALE_L2E;
            float t1 = sacc[nt][1] * SCALE_L2E;
            float t2 = sacc[nt][2] * SCALE_L2E;
            float t3 = sacc[nt][3] * SCALE_L2E;
            if (diag) {
                int c0 = nt * 8 + 2 * (lane & 3);
                if (c0 > rrel0) t0 = -1e30f;
                if (c0 + 1 > rrel0) t1 = -1e30f;
                if (c0 > rrel1) t2 = -1e30f;
                if (c0 + 1 > rrel1) t3 = -1e30f;
            }
            sacc[nt][0] = t0; sacc[nt][1] = t1;
            sacc[nt][2] = t2; sacc[nt][3] = t3;
            mx0 = fmaxf(mx0, fmaxf(t0, t1));
            mx1 = fmaxf(mx1, fmaxf(t2, t3));
        }
        mx0 = fmaxf(mx0, __shfl_xor_sync(0xffffffffu, mx0, 1));
        mx0 = fmaxf(mx0, __shfl_xor_sync(0xffffffffu, mx0, 2));
        mx1 = fmaxf(mx1, __shfl_xor_sync(0xffffffffu, mx1, 1));
        mx1 = fmaxf(mx1, __shfl_xor_sync(0xffffffffu, mx1, 2));
        float mnew0 = fmaxf(rowm0, mx0);
        float mnew1 = fmaxf(rowm1, mx1);
        float a0 = ex2(rowm0 - mnew0);
        float a1 = ex2(rowm1 - mnew1);
        float sum0 = 0.0f, sum1 = 0.0f;
#pragma unroll
        for (int nt = 0; nt < 8; nt++) {
            float p0 = ex2(sacc[nt][0] - mnew0);
            float p1 = ex2(sacc[nt][1] - mnew0);
            float p2 = ex2(sacc[nt][2] - mnew1);
            float p3 = ex2(sacc[nt][3] - mnew1);
            sacc[nt][0] = p0; sacc[nt][1] = p1;
            sacc[nt][2] = p2; sacc[nt][3] = p3;
            sum0 += p0 + p1;
            sum1 += p2 + p3;
        }
        sum0 += __shfl_xor_sync(0xffffffffu, sum0, 1);
        sum0 += __shfl_xor_sync(0xffffffffu, sum0, 2);
        sum1 += __shfl_xor_sync(0xffffffffu, sum1, 1);
        sum1 += __shfl_xor_sync(0xffffffffu, sum1, 2);
        rowl0 = rowl0 * a0 + sum0;
        rowl1 = rowl1 * a1 + sum1;
        rowm0 = mnew0;
        rowm1 = mnew1;
#pragma unroll
        for (int nt = 0; nt < 8; nt++) {
            oacc[nt][0] *= a0; oacc[nt][1] *= a0;
            oacc[nt][2] *= a1; oacc[nt][3] *= a1;
        }

        // ---- O += P V (2-pass: ph*vh + pl*vh) ----
#pragma unroll
        for (int ks2 = 0; ks2 < 4; ks2++) {
            uint32_t aph[4], apl[4];
            split2h(sacc[2 * ks2][0], sacc[2 * ks2][1], aph[0], apl[0]);
            split2h(sacc[2 * ks2][2], sacc[2 * ks2][3], aph[1], apl[1]);
            split2h(sacc[2 * ks2 + 1][0], sacc[2 * ks2 + 1][1], aph[2], apl[2]);
            split2h(sacc[2 * ks2 + 1][2], sacc[2 * ks2 + 1][3], aph[3], apl[3]);
#pragma unroll
            for (int nt16 = 0; nt16 < 4; nt16++) {
                uint32_t vbh[4];
                uint32_t vd = stage + FTILE + (ks2 * 16 + vrow) * 144
                            + nt16 * 32 + vcb;
                LDSM_X4_T(vbh, vd);
                mma_f16(oacc[2 * nt16], aph, &vbh[0]);
                mma_f16(oacc[2 * nt16], apl, &vbh[0]);
                mma_f16(oacc[2 * nt16 + 1], aph, &vbh[2]);
                mma_f16(oacc[2 * nt16 + 1], apl, &vbh[2]);
            }
        }
        __syncthreads();
    }

    // ---- epilogue: normalize, write f16 hi/lo into g_ah/g_al slice 0 ----
    float inv0 = 1.0f / rowl0;
    float inv1 = 1.0f / rowl1;
    int b = bhid >> 4, h = bhid & 15;
    int row0 = b * Ss + qtile * 64 + rrel0;
    int row1 = row0 + 8;
#pragma unroll
    for (int nt = 0; nt < 8; nt++) {
        int col = h * 64 + nt * 8 + 2 * (lane & 3);
        uint32_t ph, pl;
        split2h(oacc[nt][0] * inv0, oacc[nt][1] * inv0, ph, pl);
        *(uint32_t*)&g_ah[(size_t)row0 * Dd + col] = ph;
        *(uint32_t*)&g_al[(size_t)row0 * Dd + col] = pl;
        split2h(oacc[nt][2] * inv1, oacc[nt][3] * inv1, ph, pl);
        *(uint32_t*)&g_ah[(size_t)row1 * Dd + col] = ph;
        *(uint32_t*)&g_al[(size_t)row1 * Dd + col] = pl;
    }
}

// ---------------- launch ----------------
// Input order: K, V, Q, mask, Wk, bk, Wv, bv, Wq, bq, Wo, bo
extern "C" void kernel_launch(void* const* d_in, const int* in_sizes, int n_in,
                              void* d_out, int out_size)
{
    const float* K  = (const float*)d_in[0];
    const float* V  = (const float*)d_in[1];
    const float* Q  = (const float*)d_in[2];
    const float* Wk = (const float*)d_in[4];
    const float* bk = (const float*)d_in[5];
    const float* Wv = (const float*)d_in[6];
    const float* bv = (const float*)d_in[7];
    const float* Wq = (const float*)d_in[8];
    const float* bq = (const float*)d_in[9];
    const float* Wo = (const float*)d_in[10];
    const float* bo = (const float*)d_in[11];
    float* out = (float*)d_out;

    cudaFuncSetAttribute(gemm_qkv, cudaFuncAttributeMaxDynamicSharedMemorySize, GEMM_SMEM);
    cudaFuncSetAttribute(gemm_out, cudaFuncAttributeMaxDynamicSharedMemorySize, GEMM_SMEM);
    cudaFuncSetAttribute(flash_mma, cudaFuncAttributeMaxDynamicSharedMemorySize, FLASH_SMEM);

    split_qkv<<<dim3((Mm * Dd) / (256 * 4), 3), 256>>>(Q, K, V);
    split_w<<<dim3(Dd / 32, Dd / 32, 4), 256>>>(Wq, Wk, Wv, Wo);
    gemm_qkv<<<dim3(Dd / GBN, Mm / GBM, 3), 256, GEMM_SMEM>>>(bq, bk, bv);
    flash_mma<<<dim3(Ss / 64, Bb * Hh), 128, FLASH_SMEM>>>();
    gemm_out<<<dim3(Dd / GBN, Mm / GBM), 256, GEMM_SMEM>>>(bo, out);
}